// round 13
// baseline (speedup 1.0000x reference)
#include <cuda_runtime.h>
#include <cuda_fp16.h>
#include <cstdint>

#define B_TOTAL  4096
#define T_TOT    64
#define KDIM     192
#define DT       0.01f

#define CTA_ROWS 32
#define NTH      384          // 12 warps = 12 col-tiles of 16
#define NGRID    (B_TOTAL / CTA_ROWS)   // 128

__device__ __half g_W1h[192 * 192];   // rows 0-127 = cW1, 128-191 = rW1  ([n][k])
__device__ __half g_W2ch[128 * 128];
__device__ __half g_W2rh[64 * 64];
__device__ float  g_b1[192];
__device__ float  g_b2c[128];
__device__ float  g_b2r[64];

__global__ void pack_weights(const float* __restrict__ cW1, const float* __restrict__ cb1,
                             const float* __restrict__ cW2, const float* __restrict__ cb2,
                             const float* __restrict__ rW1, const float* __restrict__ rb1,
                             const float* __restrict__ rW2, const float* __restrict__ rb2)
{
    int i = blockIdx.x * blockDim.x + threadIdx.x;
    if (i < 192 * 192) {
        int n = i / 192, k = i % 192;
        float v = (n < 128) ? cW1[n * 192 + k] : rW1[(n - 128) * 192 + k];
        g_W1h[i] = __float2half_rn(v);
    }
    if (i < 128 * 128) g_W2ch[i] = __float2half_rn(cW2[i]);
    if (i < 64 * 64)   g_W2rh[i] = __float2half_rn(rW2[i]);
    if (i < 192) g_b1[i]  = (i < 128) ? cb1[i] : rb1[i - 128];
    if (i < 128) g_b2c[i] = cb2[i];
    if (i < 64)  g_b2r[i] = rb2[i];
}

__device__ __forceinline__ uint32_t smem_to_u32(const void* p) {
    uint32_t a;
    asm("{ .reg .u64 t; cvta.to.shared.u64 t, %1; cvt.u32.u64 %0, t; }" : "=r"(a) : "l"(p));
    return a;
}

#define LDSM4(a, addr) \
    asm volatile("ldmatrix.sync.aligned.m8n8.x4.shared.b16 {%0,%1,%2,%3}, [%4];" \
                 : "=r"((a)[0]), "=r"((a)[1]), "=r"((a)[2]), "=r"((a)[3]) : "r"(addr))

#define MMA16816(d, a, b) \
    asm volatile("mma.sync.aligned.m16n8k16.row.col.f32.f16.f16.f32 " \
                 "{%0,%1,%2,%3}, {%4,%5,%6,%7}, {%8,%9}, {%0,%1,%2,%3};" \
                 : "+f"((d)[0]), "+f"((d)[1]), "+f"((d)[2]), "+f"((d)[3]) \
                 : "r"((a)[0]), "r"((a)[1]), "r"((a)[2]), "r"((a)[3]), \
                   "r"((b)[0]), "r"((b)[1]))

#define STCG_F2(p, v) \
    asm volatile("st.global.cg.v2.f32 [%0], {%1, %2};" :: "l"(p), "f"((v).x), "f"((v).y) : "memory")

__device__ __forceinline__ float exp_t(float x) {
    return 1.f + x * (1.f + x * (0.5f + x * (0.16666667f + x * 0.041666668f)));
}
__device__ __forceinline__ float sin_t(float x) { float x2 = x * x; return x * (1.f + x2 * (-0.16666667f + x2 * 0.0083333333f)); }
__device__ __forceinline__ float cos_t(float x) { float x2 = x * x; return 1.f + x2 * (-0.5f + x2 * 0.041666668f); }

__device__ __forceinline__ uint32_t h2u(float a, float b) {
    __half2 h = __floats2half2_rn(a, b);
    return *reinterpret_cast<uint32_t*>(&h);
}

#define H_STRIDE  200
#define OFF_HH    12800
#define SMEM_TOTAL 25600

__global__ __launch_bounds__(NTH, 1)
void koopman_mma(const float* __restrict__ x, float* __restrict__ out)
{
    extern __shared__ char smem[];
    __half* y_h = (__half*)smem;
    __half* h_h = (__half*)(smem + OFF_HH);

    const int tid  = threadIdx.x;
    const int lane = tid & 31;
    const int wrp  = tid >> 5;          // 0..11, output col-tile n0 = 16*wrp
    const int gid  = lane >> 2;
    const int tig  = lane & 3;
    const int n0   = wrp * 16;
    const bool is_real = (wrp >= 8);
    const int rw   = wrp - 8;
    const int b0   = blockIdx.x * CTA_ROWS;

    // ---- register-resident B fragments, slot-permuted: slot 0 = OWN k-chunk ----
    uint32_t b1f[12][4];
    #pragma unroll
    for (int h = 0; h < 2; h++) {
        int n = n0 + 8 * h + gid;
        b1f[0][2*h]   = *(const uint32_t*)&g_W1h[n * 192 + 16 * wrp + 2 * tig];
        b1f[0][2*h+1] = *(const uint32_t*)&g_W1h[n * 192 + 16 * wrp + 8 + 2 * tig];
    }
    #pragma unroll
    for (int i = 0; i < 11; i++) {
        int kk = i + (i >= wrp);
        #pragma unroll
        for (int h = 0; h < 2; h++) {
            int n = n0 + 8 * h + gid;
            b1f[i+1][2*h]   = *(const uint32_t*)&g_W1h[n * 192 + 16 * kk + 2 * tig];
            b1f[i+1][2*h+1] = *(const uint32_t*)&g_W1h[n * 192 + 16 * kk + 8 + 2 * tig];
        }
    }
    uint32_t b2f[8][4];
    if (!is_real) {
        #pragma unroll
        for (int h = 0; h < 2; h++) {
            int n = n0 + 8 * h + gid;
            b2f[0][2*h]   = *(const uint32_t*)&g_W2ch[n * 128 + 16 * wrp + 2 * tig];
            b2f[0][2*h+1] = *(const uint32_t*)&g_W2ch[n * 128 + 16 * wrp + 8 + 2 * tig];
        }
        #pragma unroll
        for (int i = 0; i < 7; i++) {
            int kk = i + (i >= wrp);
            #pragma unroll
            for (int h = 0; h < 2; h++) {
                int n = n0 + 8 * h + gid;
                b2f[i+1][2*h]   = *(const uint32_t*)&g_W2ch[n * 128 + 16 * kk + 2 * tig];
                b2f[i+1][2*h+1] = *(const uint32_t*)&g_W2ch[n * 128 + 16 * kk + 8 + 2 * tig];
            }
        }
    } else {
        #pragma unroll
        for (int h = 0; h < 2; h++) {
            int n = n0 - 128 + 8 * h + gid;
            b2f[0][2*h]   = *(const uint32_t*)&g_W2rh[n * 64 + 16 * rw + 2 * tig];
            b2f[0][2*h+1] = *(const uint32_t*)&g_W2rh[n * 64 + 16 * rw + 8 + 2 * tig];
        }
        #pragma unroll
        for (int i = 0; i < 3; i++) {
            int kk = i + (i >= rw);
            #pragma unroll
            for (int h = 0; h < 2; h++) {
                int n = n0 - 128 + 8 * h + gid;
                b2f[i+1][2*h]   = *(const uint32_t*)&g_W2rh[n * 64 + 16 * kk + 2 * tig];
                b2f[i+1][2*h+1] = *(const uint32_t*)&g_W2rh[n * 64 + 16 * kk + 8 + 2 * tig];
            }
        }
    }

    // ---- biases ----
    float2 b1b[2], b2b[2];
    #pragma unroll
    for (int nt = 0; nt < 2; nt++) {
        int col = n0 + 8 * nt + 2 * tig;
        b1b[nt] = make_float2(g_b1[col], g_b1[col + 1]);
        b2b[nt] = is_real ? make_float2(g_b2r[col - 128], g_b2r[col - 127])
                          : make_float2(g_b2c[col],       g_b2c[col + 1]);
    }

    // ---- fp32 state in registers ----
    float2 yreg[2][2][2];   // [mt][nt][rr]: row = mt*16+rr*8+gid, col = n0+nt*8+2tig
    #pragma unroll
    for (int mt = 0; mt < 2; mt++)
        #pragma unroll
        for (int nt = 0; nt < 2; nt++)
            #pragma unroll
            for (int rr = 0; rr < 2; rr++) {
                int row = mt * 16 + rr * 8 + gid;
                int col = n0 + nt * 8 + 2 * tig;
                float2 v = *(const float2*)&x[(size_t)(b0 + row) * T_TOT * KDIM + col];
                yreg[mt][nt][rr] = v;
                *(__half2*)&y_h[row * H_STRIDE + col] = __floats2half2_rn(v.x, v.y);
            }

    float* outp = out + (size_t)(b0 + gid) * T_TOT * KDIM + n0 + 2 * tig;

    const uint32_t rowoff = ((((lane >> 3) & 1) * 8 + (lane & 7))) * (H_STRIDE * 2)
                          + (lane >> 4) * 16;
    const uint32_t yh_u = smem_to_u32(y_h) + rowoff;
    const uint32_t hh_u = smem_to_u32(h_h) + rowoff;

    for (int t = 0; t < T_TOT; t++) {
        // ---------- phase 1 own-chunk MMA (registers only) — BEFORE the barrier ----------
        float d1[2][2][4];
        #pragma unroll
        for (int mt = 0; mt < 2; mt++)
            #pragma unroll
            for (int nt = 0; nt < 2; nt++)
                #pragma unroll
                for (int e = 0; e < 4; e++) d1[mt][nt][e] = 0.f;
        {
            uint32_t aw0[4] = { h2u(yreg[0][0][0].x, yreg[0][0][0].y), h2u(yreg[0][0][1].x, yreg[0][0][1].y),
                                h2u(yreg[0][1][0].x, yreg[0][1][0].y), h2u(yreg[0][1][1].x, yreg[0][1][1].y) };
            uint32_t aw1[4] = { h2u(yreg[1][0][0].x, yreg[1][0][0].y), h2u(yreg[1][0][1].x, yreg[1][0][1].y),
                                h2u(yreg[1][1][0].x, yreg[1][1][0].y), h2u(yreg[1][1][1].x, yreg[1][1][1].y) };
            MMA16816(d1[0][0], aw0, &b1f[0][0]);
            MMA16816(d1[0][1], aw0, &b1f[0][2]);
            MMA16816(d1[1][0], aw1, &b1f[0][0]);
            MMA16816(d1[1][1], aw1, &b1f[0][2]);
        }
        __syncthreads();   // y_h (this step) visible CTA-wide

        // ---------- deferred out-store of PREVIOUS step's state (pure register source) ----------
        // Runs after the barrier: off the barrier-drain path, overlaps phase-1 LDSM window.
        if (t) {
            #pragma unroll
            for (int mt = 0; mt < 2; mt++)
                #pragma unroll
                for (int nt = 0; nt < 2; nt++)
                    #pragma unroll
                    for (int rr = 0; rr < 2; rr++)
                        STCG_F2(outp + (size_t)(mt * 16 + rr * 8) * T_TOT * KDIM + nt * 8,
                                yreg[mt][nt][rr]);
            outp += KDIM;
        }

        // ---------- phase 1 remaining 11 chunks ----------
        #pragma unroll
        for (int i = 0; i < 11; i++) {
            int kk = i + (i >= wrp);
            uint32_t a0[4], a1[4];
            LDSM4(a0, yh_u + kk * 32);
            LDSM4(a1, yh_u + (16 * H_STRIDE * 2) + kk * 32);
            MMA16816(d1[0][0], a0, &b1f[i+1][0]);
            MMA16816(d1[0][1], a0, &b1f[i+1][2]);
            MMA16816(d1[1][0], a1, &b1f[i+1][0]);
            MMA16816(d1[1][1], a1, &b1f[i+1][2]);
        }

        // ---------- epilogue 1: bias+relu -> hf2 regs + h_h ----------
        uint32_t hf2[2][4];
        #pragma unroll
        for (int mt = 0; mt < 2; mt++)
            #pragma unroll
            for (int nt = 0; nt < 2; nt++) {
                int col = n0 + 8 * nt + 2 * tig;
                int row = mt * 16 + gid;
                uint32_t ha = h2u(fmaxf(d1[mt][nt][0] + b1b[nt].x, 0.f),
                                  fmaxf(d1[mt][nt][1] + b1b[nt].y, 0.f));
                uint32_t hb = h2u(fmaxf(d1[mt][nt][2] + b1b[nt].x, 0.f),
                                  fmaxf(d1[mt][nt][3] + b1b[nt].y, 0.f));
                hf2[mt][nt * 2]     = ha;
                hf2[mt][nt * 2 + 1] = hb;
                *(uint32_t*)&h_h[row * H_STRIDE + col]       = ha;
                *(uint32_t*)&h_h[(row + 8) * H_STRIDE + col] = hb;
            }

        // ---------- phase 2 own-chunk MMA (registers only) — BEFORE the h-barrier ----------
        float d2[2][2][4];
        #pragma unroll
        for (int mt = 0; mt < 2; mt++)
            #pragma unroll
            for (int nt = 0; nt < 2; nt++)
                #pragma unroll
                for (int e = 0; e < 4; e++) d2[mt][nt][e] = 0.f;
        MMA16816(d2[0][0], hf2[0], &b2f[0][0]);
        MMA16816(d2[0][1], hf2[0], &b2f[0][2]);
        MMA16816(d2[1][0], hf2[1], &b2f[0][0]);
        MMA16816(d2[1][1], hf2[1], &b2f[0][2]);

        // split h-barrier: complex group reads/writes only h cols 0-127 (warps 0-7),
        // real group only cols 128-191 (warps 8-11). Disjoint -> named barriers.
        if (!is_real) asm volatile("bar.sync 1, 256;" ::: "memory");
        else          asm volatile("bar.sync 2, 128;" ::: "memory");

        // ---------- phase 2 remaining chunks ----------
        if (!is_real) {
            #pragma unroll
            for (int i = 0; i < 7; i++) {
                int kk = i + (i >= wrp);
                uint32_t a0[4], a1[4];
                LDSM4(a0, hh_u + kk * 32);
                LDSM4(a1, hh_u + (16 * H_STRIDE * 2) + kk * 32);
                MMA16816(d2[0][0], a0, &b2f[i+1][0]);
                MMA16816(d2[0][1], a0, &b2f[i+1][2]);
                MMA16816(d2[1][0], a1, &b2f[i+1][0]);
                MMA16816(d2[1][1], a1, &b2f[i+1][2]);
            }
        } else {
            #pragma unroll
            for (int i = 0; i < 3; i++) {
                int kk = i + (i >= rw);
                uint32_t a0[4], a1[4];
                LDSM4(a0, hh_u + 256 + kk * 32);
                LDSM4(a1, hh_u + (16 * H_STRIDE * 2) + 256 + kk * 32);
                MMA16816(d2[0][0], a0, &b2f[i+1][0]);
                MMA16816(d2[0][1], a0, &b2f[i+1][2]);
                MMA16816(d2[1][0], a1, &b2f[i+1][0]);
                MMA16816(d2[1][1], a1, &b2f[i+1][2]);
            }
        }

        // ---------- phase 3: Koopman update (registers) + y_h STS only ----------
        #pragma unroll
        for (int mt = 0; mt < 2; mt++)
            #pragma unroll
            for (int nt = 0; nt < 2; nt++) {
                int col = n0 + 8 * nt + 2 * tig;
                #pragma unroll
                for (int rr = 0; rr < 2; rr++) {
                    int row = mt * 16 + rr * 8 + gid;
                    float v0 = d2[mt][nt][2 * rr]     + b2b[nt].x;
                    float v1 = d2[mt][nt][2 * rr + 1] + b2b[nt].y;
                    float2 yp = yreg[mt][nt][rr];
                    float o0, o1;
                    if (!is_real) {
                        float e = exp_t(DT * v0);
                        float c = cos_t(DT * v1);
                        float s = sin_t(DT * v1);
                        o0 = e * (c * yp.x - s * yp.y);
                        o1 = e * (s * yp.x + c * yp.y);
                    } else {
                        o0 = yp.x * exp_t(DT * v0);
                        o1 = yp.y * exp_t(DT * v1);
                    }
                    yreg[mt][nt][rr] = make_float2(o0, o1);
                    *(__half2*)&y_h[row * H_STRIDE + col] = __floats2half2_rn(o0, o1);
                }
            }
        // out-store for this step is deferred to the next iteration (or the tail)
    }

    // ---------- tail: store final step's state ----------
    #pragma unroll
    for (int mt = 0; mt < 2; mt++)
        #pragma unroll
        for (int nt = 0; nt < 2; nt++)
            #pragma unroll
            for (int rr = 0; rr < 2; rr++)
                STCG_F2(outp + (size_t)(mt * 16 + rr * 8) * T_TOT * KDIM + nt * 8,
                        yreg[mt][nt][rr]);
}

extern "C" void kernel_launch(void* const* d_in, const int* in_sizes, int n_in,
                              void* d_out, int out_size)
{
    const float* x   = (const float*)d_in[0];
    const float* cW1 = (const float*)d_in[1];
    const float* cb1 = (const float*)d_in[2];
    const float* cW2 = (const float*)d_in[3];
    const float* cb2 = (const float*)d_in[4];
    const float* rW1 = (const float*)d_in[5];
    const float* rb1 = (const float*)d_in[6];
    const float* rW2 = (const float*)d_in[7];
    const float* rb2 = (const float*)d_in[8];
    float* out = (float*)d_out;

    pack_weights<<<(192 * 192 + 255) / 256, 256>>>(cW1, cb1, cW2, cb2, rW1, rb1, rW2, rb2);

    cudaFuncSetAttribute(koopman_mma, cudaFuncAttributeMaxDynamicSharedMemorySize, SMEM_TOTAL);
    koopman_mma<<<NGRID, NTH, SMEM_TOTAL>>>(x, out);
}

// round 15
// speedup vs baseline: 1.2530x; 1.2530x over previous
#include <cuda_runtime.h>
#include <cuda_fp16.h>
#include <cstdint>

#define B_TOTAL  4096
#define T_TOT    64
#define KDIM     192
#define DT       0.01f

#define CTA_ROWS 32
#define NTH      384          // 12 warps = 12 col-tiles of 16
#define NGRID    (B_TOTAL / CTA_ROWS)   // 128

__device__ __forceinline__ uint32_t smem_to_u32(const void* p) {
    uint32_t a;
    asm("{ .reg .u64 t; cvta.to.shared.u64 t, %1; cvt.u32.u64 %0, t; }" : "=r"(a) : "l"(p));
    return a;
}

#define LDSM4(a, addr) \
    asm volatile("ldmatrix.sync.aligned.m8n8.x4.shared.b16 {%0,%1,%2,%3}, [%4];" \
                 : "=r"((a)[0]), "=r"((a)[1]), "=r"((a)[2]), "=r"((a)[3]) : "r"(addr))

#define MMA16816(d, a, b) \
    asm volatile("mma.sync.aligned.m16n8k16.row.col.f32.f16.f16.f32 " \
                 "{%0,%1,%2,%3}, {%4,%5,%6,%7}, {%8,%9}, {%0,%1,%2,%3};" \
                 : "+f"((d)[0]), "+f"((d)[1]), "+f"((d)[2]), "+f"((d)[3]) \
                 : "r"((a)[0]), "r"((a)[1]), "r"((a)[2]), "r"((a)[3]), \
                   "r"((b)[0]), "r"((b)[1]))

#define STCG_F2(p, v) \
    asm volatile("st.global.cg.v2.f32 [%0], {%1, %2};" :: "l"(p), "f"((v).x), "f"((v).y) : "memory")

__device__ __forceinline__ float exp_t(float x) {
    return 1.f + x * (1.f + x * (0.5f + x * (0.16666667f + x * 0.041666668f)));
}
__device__ __forceinline__ float sin_t(float x) { float x2 = x * x; return x * (1.f + x2 * (-0.16666667f + x2 * 0.0083333333f)); }
__device__ __forceinline__ float cos_t(float x) { float x2 = x * x; return 1.f + x2 * (-0.5f + x2 * 0.041666668f); }

__device__ __forceinline__ uint32_t h2u(float a, float b) {
    __half2 h = __floats2half2_rn(a, b);   // lo = a, hi = b (same bits as packed _rn halves)
    return *reinterpret_cast<uint32_t*>(&h);
}

// frag word from fp32 weight row-major [n][ncols]: halves (W[n][k], W[n][k+1])
__device__ __forceinline__ uint32_t fragw(const float* __restrict__ W, int ncols, int n, int k) {
    return h2u(__ldg(&W[n * ncols + k]), __ldg(&W[n * ncols + k + 1]));
}

#define H_STRIDE  200
#define OFF_HH    12800
#define SMEM_TOTAL 25600

__global__ __launch_bounds__(NTH, 1)
void koopman_mma(const float* __restrict__ x,
                 const float* __restrict__ cW1, const float* __restrict__ cb1,
                 const float* __restrict__ cW2, const float* __restrict__ cb2,
                 const float* __restrict__ rW1, const float* __restrict__ rb1,
                 const float* __restrict__ rW2, const float* __restrict__ rb2,
                 float* __restrict__ out)
{
    extern __shared__ char smem[];
    __half* y_h = (__half*)smem;
    __half* h_h = (__half*)(smem + OFF_HH);

    const int tid  = threadIdx.x;
    const int lane = tid & 31;
    const int wrp  = tid >> 5;          // 0..11, output col-tile n0 = 16*wrp
    const int gid  = lane >> 2;
    const int tig  = lane & 3;
    const int n0   = wrp * 16;
    const bool is_real = (wrp >= 8);
    const int rw   = wrp - 8;
    const int b0   = blockIdx.x * CTA_ROWS;

    // ---- register-resident B fragments loaded DIRECTLY from fp32 inputs ----
    // slot-permuted: slot 0 = OWN k-chunk. Per warp the source matrix is uniform:
    // complex warps (n0 < 128) read cW1/cW2 rows n; real warps read rW1/rW2 rows n-128.
    const float* W1  = is_real ? rW1 : cW1;
    const int    n1o = is_real ? (n0 - 128) : n0;   // row offset into W1

    uint32_t b1f[12][4];
    #pragma unroll
    for (int h = 0; h < 2; h++) {
        int n = n1o + 8 * h + gid;
        b1f[0][2*h]   = fragw(W1, 192, n, 16 * wrp + 2 * tig);
        b1f[0][2*h+1] = fragw(W1, 192, n, 16 * wrp + 8 + 2 * tig);
    }
    #pragma unroll
    for (int i = 0; i < 11; i++) {
        int kk = i + (i >= wrp);
        #pragma unroll
        for (int h = 0; h < 2; h++) {
            int n = n1o + 8 * h + gid;
            b1f[i+1][2*h]   = fragw(W1, 192, n, 16 * kk + 2 * tig);
            b1f[i+1][2*h+1] = fragw(W1, 192, n, 16 * kk + 8 + 2 * tig);
        }
    }
    uint32_t b2f[8][4];
    if (!is_real) {
        #pragma unroll
        for (int h = 0; h < 2; h++) {
            int n = n0 + 8 * h + gid;
            b2f[0][2*h]   = fragw(cW2, 128, n, 16 * wrp + 2 * tig);
            b2f[0][2*h+1] = fragw(cW2, 128, n, 16 * wrp + 8 + 2 * tig);
        }
        #pragma unroll
        for (int i = 0; i < 7; i++) {
            int kk = i + (i >= wrp);
            #pragma unroll
            for (int h = 0; h < 2; h++) {
                int n = n0 + 8 * h + gid;
                b2f[i+1][2*h]   = fragw(cW2, 128, n, 16 * kk + 2 * tig);
                b2f[i+1][2*h+1] = fragw(cW2, 128, n, 16 * kk + 8 + 2 * tig);
            }
        }
    } else {
        #pragma unroll
        for (int h = 0; h < 2; h++) {
            int n = n0 - 128 + 8 * h + gid;
            b2f[0][2*h]   = fragw(rW2, 64, n, 16 * rw + 2 * tig);
            b2f[0][2*h+1] = fragw(rW2, 64, n, 16 * rw + 8 + 2 * tig);
        }
        #pragma unroll
        for (int i = 0; i < 3; i++) {
            int kk = i + (i >= rw);
            #pragma unroll
            for (int h = 0; h < 2; h++) {
                int n = n0 - 128 + 8 * h + gid;
                b2f[i+1][2*h]   = fragw(rW2, 64, n, 16 * kk + 2 * tig);
                b2f[i+1][2*h+1] = fragw(rW2, 64, n, 16 * kk + 8 + 2 * tig);
            }
        }
    }

    // ---- biases (direct from inputs) ----
    float2 b1b[2], b2b[2];
    #pragma unroll
    for (int nt = 0; nt < 2; nt++) {
        int col = n0 + 8 * nt + 2 * tig;
        if (!is_real) {
            b1b[nt] = make_float2(cb1[col], cb1[col + 1]);
            b2b[nt] = make_float2(cb2[col], cb2[col + 1]);
        } else {
            b1b[nt] = make_float2(rb1[col - 128], rb1[col - 127]);
            b2b[nt] = make_float2(rb2[col - 128], rb2[col - 127]);
        }
    }

    // ---- fp32 state in registers ----
    float2 yreg[2][2][2];   // [mt][nt][rr]: row = mt*16+rr*8+gid, col = n0+nt*8+2tig
    #pragma unroll
    for (int mt = 0; mt < 2; mt++)
        #pragma unroll
        for (int nt = 0; nt < 2; nt++)
            #pragma unroll
            for (int rr = 0; rr < 2; rr++) {
                int row = mt * 16 + rr * 8 + gid;
                int col = n0 + nt * 8 + 2 * tig;
                float2 v = *(const float2*)&x[(size_t)(b0 + row) * T_TOT * KDIM + col];
                yreg[mt][nt][rr] = v;
                *(__half2*)&y_h[row * H_STRIDE + col] = __floats2half2_rn(v.x, v.y);
            }

    float* outp = out + (size_t)(b0 + gid) * T_TOT * KDIM + n0 + 2 * tig;

    const uint32_t rowoff = ((((lane >> 3) & 1) * 8 + (lane & 7))) * (H_STRIDE * 2)
                          + (lane >> 4) * 16;
    const uint32_t yh_u = smem_to_u32(y_h) + rowoff;
    const uint32_t hh_u = smem_to_u32(h_h) + rowoff;

    for (int t = 0; t < T_TOT; t++) {
        // ---------- phase 1 own-chunk MMA (registers only) — BEFORE the barrier ----------
        float d1[2][2][4];
        #pragma unroll
        for (int mt = 0; mt < 2; mt++)
            #pragma unroll
            for (int nt = 0; nt < 2; nt++)
                #pragma unroll
                for (int e = 0; e < 4; e++) d1[mt][nt][e] = 0.f;
        {
            uint32_t aw0[4] = { h2u(yreg[0][0][0].x, yreg[0][0][0].y), h2u(yreg[0][0][1].x, yreg[0][0][1].y),
                                h2u(yreg[0][1][0].x, yreg[0][1][0].y), h2u(yreg[0][1][1].x, yreg[0][1][1].y) };
            uint32_t aw1[4] = { h2u(yreg[1][0][0].x, yreg[1][0][0].y), h2u(yreg[1][0][1].x, yreg[1][0][1].y),
                                h2u(yreg[1][1][0].x, yreg[1][1][0].y), h2u(yreg[1][1][1].x, yreg[1][1][1].y) };
            MMA16816(d1[0][0], aw0, &b1f[0][0]);
            MMA16816(d1[0][1], aw0, &b1f[0][2]);
            MMA16816(d1[1][0], aw1, &b1f[0][0]);
            MMA16816(d1[1][1], aw1, &b1f[0][2]);
        }
        __syncthreads();   // y_h (this step) visible CTA-wide

        // ---------- phase 1 remaining 11 chunks ----------
        #pragma unroll
        for (int i = 0; i < 11; i++) {
            int kk = i + (i >= wrp);
            uint32_t a0[4], a1[4];
            LDSM4(a0, yh_u + kk * 32);
            LDSM4(a1, yh_u + (16 * H_STRIDE * 2) + kk * 32);
            MMA16816(d1[0][0], a0, &b1f[i+1][0]);
            MMA16816(d1[0][1], a0, &b1f[i+1][2]);
            MMA16816(d1[1][0], a1, &b1f[i+1][0]);
            MMA16816(d1[1][1], a1, &b1f[i+1][2]);
        }

        // ---------- epilogue 1: bias+relu -> hf2 regs + h_h ----------
        uint32_t hf2[2][4];
        #pragma unroll
        for (int mt = 0; mt < 2; mt++)
            #pragma unroll
            for (int nt = 0; nt < 2; nt++) {
                int col = n0 + 8 * nt + 2 * tig;
                int row = mt * 16 + gid;
                uint32_t ha = h2u(fmaxf(d1[mt][nt][0] + b1b[nt].x, 0.f),
                                  fmaxf(d1[mt][nt][1] + b1b[nt].y, 0.f));
                uint32_t hb = h2u(fmaxf(d1[mt][nt][2] + b1b[nt].x, 0.f),
                                  fmaxf(d1[mt][nt][3] + b1b[nt].y, 0.f));
                hf2[mt][nt * 2]     = ha;
                hf2[mt][nt * 2 + 1] = hb;
                *(uint32_t*)&h_h[row * H_STRIDE + col]       = ha;
                *(uint32_t*)&h_h[(row + 8) * H_STRIDE + col] = hb;
            }

        // ---------- phase 2 own-chunk MMA (registers only) — BEFORE the barrier ----------
        float d2[2][2][4];
        #pragma unroll
        for (int mt = 0; mt < 2; mt++)
            #pragma unroll
            for (int nt = 0; nt < 2; nt++)
                #pragma unroll
                for (int e = 0; e < 4; e++) d2[mt][nt][e] = 0.f;
        MMA16816(d2[0][0], hf2[0], &b2f[0][0]);
        MMA16816(d2[0][1], hf2[0], &b2f[0][2]);
        MMA16816(d2[1][0], hf2[1], &b2f[0][0]);
        MMA16816(d2[1][1], hf2[1], &b2f[0][2]);
        __syncthreads();   // h_h visible CTA-wide

        // ---------- phase 2 remaining chunks ----------
        if (!is_real) {
            #pragma unroll
            for (int i = 0; i < 7; i++) {
                int kk = i + (i >= wrp);
                uint32_t a0[4], a1[4];
                LDSM4(a0, hh_u + kk * 32);
                LDSM4(a1, hh_u + (16 * H_STRIDE * 2) + kk * 32);
                MMA16816(d2[0][0], a0, &b2f[i+1][0]);
                MMA16816(d2[0][1], a0, &b2f[i+1][2]);
                MMA16816(d2[1][0], a1, &b2f[i+1][0]);
                MMA16816(d2[1][1], a1, &b2f[i+1][2]);
            }
        } else {
            #pragma unroll
            for (int i = 0; i < 3; i++) {
                int kk = i + (i >= rw);
                uint32_t a0[4], a1[4];
                LDSM4(a0, hh_u + 256 + kk * 32);
                LDSM4(a1, hh_u + (16 * H_STRIDE * 2) + 256 + kk * 32);
                MMA16816(d2[0][0], a0, &b2f[i+1][0]);
                MMA16816(d2[0][1], a0, &b2f[i+1][2]);
                MMA16816(d2[1][0], a1, &b2f[i+1][0]);
                MMA16816(d2[1][1], a1, &b2f[i+1][2]);
            }
        }

        // ---------- phase 3: Koopman update + stores ----------
        #pragma unroll
        for (int mt = 0; mt < 2; mt++)
            #pragma unroll
            for (int nt = 0; nt < 2; nt++) {
                int col = n0 + 8 * nt + 2 * tig;
                #pragma unroll
                for (int rr = 0; rr < 2; rr++) {
                    int row = mt * 16 + rr * 8 + gid;
                    float v0 = d2[mt][nt][2 * rr]     + b2b[nt].x;
                    float v1 = d2[mt][nt][2 * rr + 1] + b2b[nt].y;
                    float2 yp = yreg[mt][nt][rr];
                    float o0, o1;
                    if (!is_real) {
                        float e = exp_t(DT * v0);
                        float c = cos_t(DT * v1);
                        float s = sin_t(DT * v1);
                        o0 = e * (c * yp.x - s * yp.y);
                        o1 = e * (s * yp.x + c * yp.y);
                    } else {
                        o0 = yp.x * exp_t(DT * v0);
                        o1 = yp.y * exp_t(DT * v1);
                    }
                    yreg[mt][nt][rr] = make_float2(o0, o1);
                    *(__half2*)&y_h[row * H_STRIDE + col] = __floats2half2_rn(o0, o1);
                    float2 ov = make_float2(o0, o1);
                    STCG_F2(outp + (size_t)(mt * 16 + rr * 8) * T_TOT * KDIM + nt * 8, ov);
                }
            }
        outp += KDIM;
        // no trailing barrier: next iteration's top barrier orders y_h writes vs reads
    }
}

extern "C" void kernel_launch(void* const* d_in, const int* in_sizes, int n_in,
                              void* d_out, int out_size)
{
    const float* x   = (const float*)d_in[0];
    const float* cW1 = (const float*)d_in[1];
    const float* cb1 = (const float*)d_in[2];
    const float* cW2 = (const float*)d_in[3];
    const float* cb2 = (const float*)d_in[4];
    const float* rW1 = (const float*)d_in[5];
    const float* rb1 = (const float*)d_in[6];
    const float* rW2 = (const float*)d_in[7];
    const float* rb2 = (const float*)d_in[8];
    float* out = (float*)d_out;

    cudaFuncSetAttribute(koopman_mma, cudaFuncAttributeMaxDynamicSharedMemorySize, SMEM_TOTAL);
    koopman_mma<<<NGRID, NTH, SMEM_TOTAL>>>(x, cW1, cb1, cW2, cb2, rW1, rb1, rW2, rb2, out);
}

// round 16
// speedup vs baseline: 1.2678x; 1.0118x over previous
#include <cuda_runtime.h>
#include <cuda_fp16.h>
#include <cstdint>

#define B_TOTAL  4096
#define T_TOT    64
#define KDIM     192
#define DT       0.01f

#define CTA_ROWS 32
#define NTH      384          // 12 warps = 12 col-tiles of 16
#define NGRID    (B_TOTAL / CTA_ROWS)   // 128

__device__ __half g_W1h[192 * 192];   // rows 0-127 = cW1, 128-191 = rW1  ([n][k])
__device__ __half g_W2ch[128 * 128];
__device__ __half g_W2rh[64 * 64];
__device__ float  g_b1[192];
__device__ float  g_b2c[128];
__device__ float  g_b2r[64];

__global__ void pack_weights(const float* __restrict__ cW1, const float* __restrict__ cb1,
                             const float* __restrict__ cW2, const float* __restrict__ cb2,
                             const float* __restrict__ rW1, const float* __restrict__ rb1,
                             const float* __restrict__ rW2, const float* __restrict__ rb2)
{
    int i = blockIdx.x * blockDim.x + threadIdx.x;
    if (i < 192 * 192) {
        int n = i / 192, k = i % 192;
        float v = (n < 128) ? cW1[n * 192 + k] : rW1[(n - 128) * 192 + k];
        g_W1h[i] = __float2half_rn(v);
    }
    if (i < 128 * 128) g_W2ch[i] = __float2half_rn(cW2[i]);
    if (i < 64 * 64)   g_W2rh[i] = __float2half_rn(rW2[i]);
    if (i < 192) g_b1[i]  = (i < 128) ? cb1[i] : rb1[i - 128];
    if (i < 128) g_b2c[i] = cb2[i];
    if (i < 64)  g_b2r[i] = rb2[i];
}

__device__ __forceinline__ uint32_t smem_to_u32(const void* p) {
    uint32_t a;
    asm("{ .reg .u64 t; cvta.to.shared.u64 t, %1; cvt.u32.u64 %0, t; }" : "=r"(a) : "l"(p));
    return a;
}

#define LDSM4(a, addr) \
    asm volatile("ldmatrix.sync.aligned.m8n8.x4.shared.b16 {%0,%1,%2,%3}, [%4];" \
                 : "=r"((a)[0]), "=r"((a)[1]), "=r"((a)[2]), "=r"((a)[3]) : "r"(addr))

#define MMA16816(d, a, b) \
    asm volatile("mma.sync.aligned.m16n8k16.row.col.f32.f16.f16.f32 " \
                 "{%0,%1,%2,%3}, {%4,%5,%6,%7}, {%8,%9}, {%0,%1,%2,%3};" \
                 : "+f"((d)[0]), "+f"((d)[1]), "+f"((d)[2]), "+f"((d)[3]) \
                 : "r"((a)[0]), "r"((a)[1]), "r"((a)[2]), "r"((a)[3]), \
                   "r"((b)[0]), "r"((b)[1]))

#define STCG_F2(p, v) \
    asm volatile("st.global.cg.v2.f32 [%0], {%1, %2};" :: "l"(p), "f"((v).x), "f"((v).y) : "memory")

__device__ __forceinline__ float exp_t(float x) {
    return 1.f + x * (1.f + x * (0.5f + x * (0.16666667f + x * 0.041666668f)));
}
__device__ __forceinline__ float sin_t(float x) { float x2 = x * x; return x * (1.f + x2 * (-0.16666667f + x2 * 0.0083333333f)); }
__device__ __forceinline__ float cos_t(float x) { float x2 = x * x; return 1.f + x2 * (-0.5f + x2 * 0.041666668f); }

__device__ __forceinline__ uint32_t h2u(float a, float b) {
    __half2 h = __floats2half2_rn(a, b);
    return *reinterpret_cast<uint32_t*>(&h);
}

#define H_STRIDE  200
#define OFF_HH    12800
#define SMEM_TOTAL 25600

__global__ __launch_bounds__(NTH, 1)
void koopman_mma(const float* __restrict__ x, float* __restrict__ out)
{
    extern __shared__ char smem[];
    __half* y_h = (__half*)smem;
    __half* h_h = (__half*)(smem + OFF_HH);

    const int tid  = threadIdx.x;
    const int lane = tid & 31;
    const int wrp  = tid >> 5;          // 0..11, output col-tile n0 = 16*wrp
    const int gid  = lane >> 2;
    const int tig  = lane & 3;
    const int n0   = wrp * 16;
    const bool is_real = (wrp >= 8);
    const int rw   = wrp - 8;
    const int b0   = blockIdx.x * CTA_ROWS;

    // ---- register-resident B fragments, slot-permuted: slot 0 = OWN k-chunk ----
    uint32_t b1f[12][4];
    #pragma unroll
    for (int h = 0; h < 2; h++) {
        int n = n0 + 8 * h + gid;
        b1f[0][2*h]   = *(const uint32_t*)&g_W1h[n * 192 + 16 * wrp + 2 * tig];
        b1f[0][2*h+1] = *(const uint32_t*)&g_W1h[n * 192 + 16 * wrp + 8 + 2 * tig];
    }
    #pragma unroll
    for (int i = 0; i < 11; i++) {
        int kk = i + (i >= wrp);
        #pragma unroll
        for (int h = 0; h < 2; h++) {
            int n = n0 + 8 * h + gid;
            b1f[i+1][2*h]   = *(const uint32_t*)&g_W1h[n * 192 + 16 * kk + 2 * tig];
            b1f[i+1][2*h+1] = *(const uint32_t*)&g_W1h[n * 192 + 16 * kk + 8 + 2 * tig];
        }
    }
    uint32_t b2f[8][4];
    if (!is_real) {
        #pragma unroll
        for (int h = 0; h < 2; h++) {
            int n = n0 + 8 * h + gid;
            b2f[0][2*h]   = *(const uint32_t*)&g_W2ch[n * 128 + 16 * wrp + 2 * tig];
            b2f[0][2*h+1] = *(const uint32_t*)&g_W2ch[n * 128 + 16 * wrp + 8 + 2 * tig];
        }
        #pragma unroll
        for (int i = 0; i < 7; i++) {
            int kk = i + (i >= wrp);
            #pragma unroll
            for (int h = 0; h < 2; h++) {
                int n = n0 + 8 * h + gid;
                b2f[i+1][2*h]   = *(const uint32_t*)&g_W2ch[n * 128 + 16 * kk + 2 * tig];
                b2f[i+1][2*h+1] = *(const uint32_t*)&g_W2ch[n * 128 + 16 * kk + 8 + 2 * tig];
            }
        }
    } else {
        #pragma unroll
        for (int h = 0; h < 2; h++) {
            int n = n0 - 128 + 8 * h + gid;
            b2f[0][2*h]   = *(const uint32_t*)&g_W2rh[n * 64 + 16 * rw + 2 * tig];
            b2f[0][2*h+1] = *(const uint32_t*)&g_W2rh[n * 64 + 16 * rw + 8 + 2 * tig];
        }
        #pragma unroll
        for (int i = 0; i < 3; i++) {
            int kk = i + (i >= rw);
            #pragma unroll
            for (int h = 0; h < 2; h++) {
                int n = n0 - 128 + 8 * h + gid;
                b2f[i+1][2*h]   = *(const uint32_t*)&g_W2rh[n * 64 + 16 * kk + 2 * tig];
                b2f[i+1][2*h+1] = *(const uint32_t*)&g_W2rh[n * 64 + 16 * kk + 8 + 2 * tig];
            }
        }
    }

    // ---- biases ----
    float2 b1b[2], b2b[2];
    #pragma unroll
    for (int nt = 0; nt < 2; nt++) {
        int col = n0 + 8 * nt + 2 * tig;
        b1b[nt] = make_float2(g_b1[col], g_b1[col + 1]);
        b2b[nt] = is_real ? make_float2(g_b2r[col - 128], g_b2r[col - 127])
                          : make_float2(g_b2c[col],       g_b2c[col + 1]);
    }

    // ---- fp32 state in registers ----
    float2 yreg[2][2][2];   // [mt][nt][rr]: row = mt*16+rr*8+gid, col = n0+nt*8+2tig
    #pragma unroll
    for (int mt = 0; mt < 2; mt++)
        #pragma unroll
        for (int nt = 0; nt < 2; nt++)
            #pragma unroll
            for (int rr = 0; rr < 2; rr++) {
                int row = mt * 16 + rr * 8 + gid;
                int col = n0 + nt * 8 + 2 * tig;
                float2 v = *(const float2*)&x[(size_t)(b0 + row) * T_TOT * KDIM + col];
                yreg[mt][nt][rr] = v;
                *(__half2*)&y_h[row * H_STRIDE + col] = __floats2half2_rn(v.x, v.y);
            }

    float* outp = out + (size_t)(b0 + gid) * T_TOT * KDIM + n0 + 2 * tig;

    const uint32_t rowoff = ((((lane >> 3) & 1) * 8 + (lane & 7))) * (H_STRIDE * 2)
                          + (lane >> 4) * 16;
    const uint32_t yh_u = smem_to_u32(y_h) + rowoff;
    const uint32_t hh_u = smem_to_u32(h_h) + rowoff;

    for (int t = 0; t < T_TOT; t++) {
        // ---------- phase 1 own-chunk MMA (registers only) — BEFORE the barrier ----------
        float d1[2][2][4];
        #pragma unroll
        for (int mt = 0; mt < 2; mt++)
            #pragma unroll
            for (int nt = 0; nt < 2; nt++)
                #pragma unroll
                for (int e = 0; e < 4; e++) d1[mt][nt][e] = 0.f;
        {
            uint32_t aw0[4] = { h2u(yreg[0][0][0].x, yreg[0][0][0].y), h2u(yreg[0][0][1].x, yreg[0][0][1].y),
                                h2u(yreg[0][1][0].x, yreg[0][1][0].y), h2u(yreg[0][1][1].x, yreg[0][1][1].y) };
            uint32_t aw1[4] = { h2u(yreg[1][0][0].x, yreg[1][0][0].y), h2u(yreg[1][0][1].x, yreg[1][0][1].y),
                                h2u(yreg[1][1][0].x, yreg[1][1][0].y), h2u(yreg[1][1][1].x, yreg[1][1][1].y) };
            MMA16816(d1[0][0], aw0, &b1f[0][0]);
            MMA16816(d1[0][1], aw0, &b1f[0][2]);
            MMA16816(d1[1][0], aw1, &b1f[0][0]);
            MMA16816(d1[1][1], aw1, &b1f[0][2]);
        }
        __syncthreads();   // y_h (this step) visible CTA-wide

        // ---------- phase 1 remaining 11 chunks ----------
        #pragma unroll
        for (int i = 0; i < 11; i++) {
            int kk = i + (i >= wrp);
            uint32_t a0[4], a1[4];
            LDSM4(a0, yh_u + kk * 32);
            LDSM4(a1, yh_u + (16 * H_STRIDE * 2) + kk * 32);
            MMA16816(d1[0][0], a0, &b1f[i+1][0]);
            MMA16816(d1[0][1], a0, &b1f[i+1][2]);
            MMA16816(d1[1][0], a1, &b1f[i+1][0]);
            MMA16816(d1[1][1], a1, &b1f[i+1][2]);
        }

        // ---------- epilogue 1: bias+relu -> hf2 regs + h_h ----------
        uint32_t hf2[2][4];
        #pragma unroll
        for (int mt = 0; mt < 2; mt++)
            #pragma unroll
            for (int nt = 0; nt < 2; nt++) {
                int col = n0 + 8 * nt + 2 * tig;
                int row = mt * 16 + gid;
                uint32_t ha = h2u(fmaxf(d1[mt][nt][0] + b1b[nt].x, 0.f),
                                  fmaxf(d1[mt][nt][1] + b1b[nt].y, 0.f));
                uint32_t hb = h2u(fmaxf(d1[mt][nt][2] + b1b[nt].x, 0.f),
                                  fmaxf(d1[mt][nt][3] + b1b[nt].y, 0.f));
                hf2[mt][nt * 2]     = ha;
                hf2[mt][nt * 2 + 1] = hb;
                *(uint32_t*)&h_h[row * H_STRIDE + col]       = ha;
                *(uint32_t*)&h_h[(row + 8) * H_STRIDE + col] = hb;
            }

        // ---------- phase 2 own-chunk MMA (registers only) — BEFORE the h-barrier ----------
        float d2[2][2][4];
        #pragma unroll
        for (int mt = 0; mt < 2; mt++)
            #pragma unroll
            for (int nt = 0; nt < 2; nt++)
                #pragma unroll
                for (int e = 0; e < 4; e++) d2[mt][nt][e] = 0.f;
        MMA16816(d2[0][0], hf2[0], &b2f[0][0]);
        MMA16816(d2[0][1], hf2[0], &b2f[0][2]);
        MMA16816(d2[1][0], hf2[1], &b2f[0][0]);
        MMA16816(d2[1][1], hf2[1], &b2f[0][2]);

        // split h-barrier: complex group (warps 0-7) touches only h cols 0-127,
        // real group (warps 8-11) only cols 128-191; disjoint -> named barriers.
        // Cross-step ordering is handled by the full __syncthreads at loop top.
        if (!is_real) asm volatile("bar.sync 1, 256;" ::: "memory");
        else          asm volatile("bar.sync 2, 128;" ::: "memory");

        // ---------- phase 2 remaining chunks ----------
        if (!is_real) {
            #pragma unroll
            for (int i = 0; i < 7; i++) {
                int kk = i + (i >= wrp);
                uint32_t a0[4], a1[4];
                LDSM4(a0, hh_u + kk * 32);
                LDSM4(a1, hh_u + (16 * H_STRIDE * 2) + kk * 32);
                MMA16816(d2[0][0], a0, &b2f[i+1][0]);
                MMA16816(d2[0][1], a0, &b2f[i+1][2]);
                MMA16816(d2[1][0], a1, &b2f[i+1][0]);
                MMA16816(d2[1][1], a1, &b2f[i+1][2]);
            }
        } else {
            #pragma unroll
            for (int i = 0; i < 3; i++) {
                int kk = i + (i >= rw);
                uint32_t a0[4], a1[4];
                LDSM4(a0, hh_u + 256 + kk * 32);
                LDSM4(a1, hh_u + (16 * H_STRIDE * 2) + 256 + kk * 32);
                MMA16816(d2[0][0], a0, &b2f[i+1][0]);
                MMA16816(d2[0][1], a0, &b2f[i+1][2]);
                MMA16816(d2[1][0], a1, &b2f[i+1][0]);
                MMA16816(d2[1][1], a1, &b2f[i+1][2]);
            }
        }

        // ---------- phase 3: Koopman update + stores ----------
        #pragma unroll
        for (int mt = 0; mt < 2; mt++)
            #pragma unroll
            for (int nt = 0; nt < 2; nt++) {
                int col = n0 + 8 * nt + 2 * tig;
                #pragma unroll
                for (int rr = 0; rr < 2; rr++) {
                    int row = mt * 16 + rr * 8 + gid;
                    float v0 = d2[mt][nt][2 * rr]     + b2b[nt].x;
                    float v1 = d2[mt][nt][2 * rr + 1] + b2b[nt].y;
                    float2 yp = yreg[mt][nt][rr];
                    float o0, o1;
                    if (!is_real) {
                        float e = exp_t(DT * v0);
                        float c = cos_t(DT * v1);
                        float s = sin_t(DT * v1);
                        o0 = e * (c * yp.x - s * yp.y);
                        o1 = e * (s * yp.x + c * yp.y);
                    } else {
                        o0 = yp.x * exp_t(DT * v0);
                        o1 = yp.y * exp_t(DT * v1);
                    }
                    yreg[mt][nt][rr] = make_float2(o0, o1);
                    *(__half2*)&y_h[row * H_STRIDE + col] = __floats2half2_rn(o0, o1);
                    float2 ov = make_float2(o0, o1);
                    STCG_F2(outp + (size_t)(mt * 16 + rr * 8) * T_TOT * KDIM + nt * 8, ov);
                }
            }
        outp += KDIM;
        // no trailing barrier: next iteration's top barrier orders y_h writes vs reads
    }
}

extern "C" void kernel_launch(void* const* d_in, const int* in_sizes, int n_in,
                              void* d_out, int out_size)
{
    const float* x   = (const float*)d_in[0];
    const float* cW1 = (const float*)d_in[1];
    const float* cb1 = (const float*)d_in[2];
    const float* cW2 = (const float*)d_in[3];
    const float* cb2 = (const float*)d_in[4];
    const float* rW1 = (const float*)d_in[5];
    const float* rb1 = (const float*)d_in[6];
    const float* rW2 = (const float*)d_in[7];
    const float* rb2 = (const float*)d_in[8];
    float* out = (float*)d_out;

    pack_weights<<<(192 * 192 + 255) / 256, 256>>>(cW1, cb1, cW2, cb2, rW1, rb1, rW2, rb2);

    cudaFuncSetAttribute(koopman_mma, cudaFuncAttributeMaxDynamicSharedMemorySize, SMEM_TOTAL);
    koopman_mma<<<NGRID, NTH, SMEM_TOTAL>>>(x, out);
}

// round 17
// speedup vs baseline: 1.2783x; 1.0083x over previous
#include <cuda_runtime.h>
#include <cuda_fp16.h>
#include <cstdint>

#define B_TOTAL  4096
#define T_TOT    64
#define KDIM     192
#define DT       0.01f

#define CTA_ROWS 32
#define NTH      384          // 12 warps = 12 col-tiles of 16
#define NGRID    (B_TOTAL / CTA_ROWS)   // 128

__device__ __half g_W1h[192 * 192];   // rows 0-127 = cW1, 128-191 = rW1  ([n][k])
__device__ __half g_W2ch[128 * 128];
__device__ __half g_W2rh[64 * 64];
__device__ float  g_b1[192];
__device__ float  g_b2c[128];
__device__ float  g_b2r[64];

__global__ void pack_weights(const float* __restrict__ cW1, const float* __restrict__ cb1,
                             const float* __restrict__ cW2, const float* __restrict__ cb2,
                             const float* __restrict__ rW1, const float* __restrict__ rb1,
                             const float* __restrict__ rW2, const float* __restrict__ rb2)
{
    int i = blockIdx.x * blockDim.x + threadIdx.x;
    if (i < 192 * 192) {
        int n = i / 192, k = i % 192;
        float v = (n < 128) ? cW1[n * 192 + k] : rW1[(n - 128) * 192 + k];
        g_W1h[i] = __float2half_rn(v);
    }
    if (i < 128 * 128) g_W2ch[i] = __float2half_rn(cW2[i]);
    if (i < 64 * 64)   g_W2rh[i] = __float2half_rn(rW2[i]);
    if (i < 192) g_b1[i]  = (i < 128) ? cb1[i] : rb1[i - 128];
    if (i < 128) g_b2c[i] = cb2[i];
    if (i < 64)  g_b2r[i] = rb2[i];
}

__device__ __forceinline__ uint32_t smem_to_u32(const void* p) {
    uint32_t a;
    asm("{ .reg .u64 t; cvta.to.shared.u64 t, %1; cvt.u32.u64 %0, t; }" : "=r"(a) : "l"(p));
    return a;
}

#define LDSM4(a, addr) \
    asm volatile("ldmatrix.sync.aligned.m8n8.x4.shared.b16 {%0,%1,%2,%3}, [%4];" \
                 : "=r"((a)[0]), "=r"((a)[1]), "=r"((a)[2]), "=r"((a)[3]) : "r"(addr))

#define MMA16816(d, a, b) \
    asm volatile("mma.sync.aligned.m16n8k16.row.col.f32.f16.f16.f32 " \
                 "{%0,%1,%2,%3}, {%4,%5,%6,%7}, {%8,%9}, {%0,%1,%2,%3};" \
                 : "+f"((d)[0]), "+f"((d)[1]), "+f"((d)[2]), "+f"((d)[3]) \
                 : "r"((a)[0]), "r"((a)[1]), "r"((a)[2]), "r"((a)[3]), \
                   "r"((b)[0]), "r"((b)[1]))

#define STCG_F2(p, v) \
    asm volatile("st.global.cg.v2.f32 [%0], {%1, %2};" :: "l"(p), "f"((v).x), "f"((v).y) : "memory")

__device__ __forceinline__ float exp_t(float x) {
    return 1.f + x * (1.f + x * (0.5f + x * (0.16666667f + x * 0.041666668f)));
}
__device__ __forceinline__ float sin_t(float x) { float x2 = x * x; return x * (1.f + x2 * (-0.16666667f + x2 * 0.0083333333f)); }
__device__ __forceinline__ float cos_t(float x) { float x2 = x * x; return 1.f + x2 * (-0.5f + x2 * 0.041666668f); }

__device__ __forceinline__ uint32_t h2u(float a, float b) {
    __half2 h = __floats2half2_rn(a, b);
    return *reinterpret_cast<uint32_t*>(&h);
}

#define H_STRIDE  200
#define OFF_HH    12800
#define SMEM_TOTAL 25600
#define GOFF      (16 * H_STRIDE * 2)   // byte offset of group B's 16 rows

__global__ __launch_bounds__(NTH, 1)
void koopman_mma(const float* __restrict__ x, float* __restrict__ out)
{
    extern __shared__ char smem[];
    __half* y_h = (__half*)smem;
    __half* h_h = (__half*)(smem + OFF_HH);

    const int tid  = threadIdx.x;
    const int lane = tid & 31;
    const int wrp  = tid >> 5;          // 0..11, output col-tile n0 = 16*wrp
    const int gid  = lane >> 2;
    const int tig  = lane & 3;
    const int n0   = wrp * 16;
    const bool is_real = (wrp >= 8);
    const int rw   = wrp - 8;
    const int b0   = blockIdx.x * CTA_ROWS;

    // ---- register-resident B fragments, slot-permuted: slot 0 = OWN k-chunk ----
    uint32_t b1f[12][4];
    #pragma unroll
    for (int h = 0; h < 2; h++) {
        int n = n0 + 8 * h + gid;
        b1f[0][2*h]   = *(const uint32_t*)&g_W1h[n * 192 + 16 * wrp + 2 * tig];
        b1f[0][2*h+1] = *(const uint32_t*)&g_W1h[n * 192 + 16 * wrp + 8 + 2 * tig];
    }
    #pragma unroll
    for (int i = 0; i < 11; i++) {
        int kk = i + (i >= wrp);
        #pragma unroll
        for (int h = 0; h < 2; h++) {
            int n = n0 + 8 * h + gid;
            b1f[i+1][2*h]   = *(const uint32_t*)&g_W1h[n * 192 + 16 * kk + 2 * tig];
            b1f[i+1][2*h+1] = *(const uint32_t*)&g_W1h[n * 192 + 16 * kk + 8 + 2 * tig];
        }
    }
    uint32_t b2f[8][4];
    if (!is_real) {
        #pragma unroll
        for (int h = 0; h < 2; h++) {
            int n = n0 + 8 * h + gid;
            b2f[0][2*h]   = *(const uint32_t*)&g_W2ch[n * 128 + 16 * wrp + 2 * tig];
            b2f[0][2*h+1] = *(const uint32_t*)&g_W2ch[n * 128 + 16 * wrp + 8 + 2 * tig];
        }
        #pragma unroll
        for (int i = 0; i < 7; i++) {
            int kk = i + (i >= wrp);
            #pragma unroll
            for (int h = 0; h < 2; h++) {
                int n = n0 + 8 * h + gid;
                b2f[i+1][2*h]   = *(const uint32_t*)&g_W2ch[n * 128 + 16 * kk + 2 * tig];
                b2f[i+1][2*h+1] = *(const uint32_t*)&g_W2ch[n * 128 + 16 * kk + 8 + 2 * tig];
            }
        }
    } else {
        #pragma unroll
        for (int h = 0; h < 2; h++) {
            int n = n0 - 128 + 8 * h + gid;
            b2f[0][2*h]   = *(const uint32_t*)&g_W2rh[n * 64 + 16 * rw + 2 * tig];
            b2f[0][2*h+1] = *(const uint32_t*)&g_W2rh[n * 64 + 16 * rw + 8 + 2 * tig];
        }
        #pragma unroll
        for (int i = 0; i < 3; i++) {
            int kk = i + (i >= rw);
            #pragma unroll
            for (int h = 0; h < 2; h++) {
                int n = n0 - 128 + 8 * h + gid;
                b2f[i+1][2*h]   = *(const uint32_t*)&g_W2rh[n * 64 + 16 * kk + 2 * tig];
                b2f[i+1][2*h+1] = *(const uint32_t*)&g_W2rh[n * 64 + 16 * kk + 8 + 2 * tig];
            }
        }
    }

    // ---- biases ----
    float2 b1b[2], b2b[2];
    #pragma unroll
    for (int nt = 0; nt < 2; nt++) {
        int col = n0 + 8 * nt + 2 * tig;
        b1b[nt] = make_float2(g_b1[col], g_b1[col + 1]);
        b2b[nt] = is_real ? make_float2(g_b2r[col - 128], g_b2r[col - 127])
                          : make_float2(g_b2c[col],       g_b2c[col + 1]);
    }

    // ---- fp32 state in registers: yreg[g][nt][rr], g = 16-row group ----
    float2 yreg[2][2][2];
    #pragma unroll
    for (int g = 0; g < 2; g++)
        #pragma unroll
        for (int nt = 0; nt < 2; nt++)
            #pragma unroll
            for (int rr = 0; rr < 2; rr++) {
                int row = g * 16 + rr * 8 + gid;
                int col = n0 + nt * 8 + 2 * tig;
                float2 v = *(const float2*)&x[(size_t)(b0 + row) * T_TOT * KDIM + col];
                yreg[g][nt][rr] = v;
                *(__half2*)&y_h[row * H_STRIDE + col] = __floats2half2_rn(v.x, v.y);
            }

    float* outp = out + (size_t)(b0 + gid) * T_TOT * KDIM + n0 + 2 * tig;

    const uint32_t rowoff = ((((lane >> 3) & 1) * 8 + (lane & 7))) * (H_STRIDE * 2)
                          + (lane >> 4) * 16;
    const uint32_t yh_u = smem_to_u32(y_h) + rowoff;
    const uint32_t hh_u = smem_to_u32(h_h) + rowoff;

    float d1A[2][4], d1B[2][4], d2A[2][4], d2B[2][4];
    uint32_t hf2A[4], hf2B[4];

    // ---- helper lambdas (all fully inlined) ----
    auto own1f = [&](float (&d1)[2][4], int g) {
        #pragma unroll
        for (int nt = 0; nt < 2; nt++)
            #pragma unroll
            for (int e = 0; e < 4; e++) d1[nt][e] = 0.f;
        uint32_t aw[4] = { h2u(yreg[g][0][0].x, yreg[g][0][0].y), h2u(yreg[g][0][1].x, yreg[g][0][1].y),
                           h2u(yreg[g][1][0].x, yreg[g][1][0].y), h2u(yreg[g][1][1].x, yreg[g][1][1].y) };
        MMA16816(d1[0], aw, &b1f[0][0]);
        MMA16816(d1[1], aw, &b1f[0][2]);
    };
    auto e1f = [&](float (&d1)[2][4], uint32_t (&hf)[4], int g) {
        #pragma unroll
        for (int nt = 0; nt < 2; nt++) {
            int col = n0 + 8 * nt + 2 * tig;
            int row = g * 16 + gid;
            uint32_t ha = h2u(fmaxf(d1[nt][0] + b1b[nt].x, 0.f), fmaxf(d1[nt][1] + b1b[nt].y, 0.f));
            uint32_t hb = h2u(fmaxf(d1[nt][2] + b1b[nt].x, 0.f), fmaxf(d1[nt][3] + b1b[nt].y, 0.f));
            hf[nt * 2]     = ha;
            hf[nt * 2 + 1] = hb;
            *(uint32_t*)&h_h[row * H_STRIDE + col]       = ha;
            *(uint32_t*)&h_h[(row + 8) * H_STRIDE + col] = hb;
        }
    };
    auto own2f = [&](float (&d2)[2][4], uint32_t (&hf)[4]) {
        #pragma unroll
        for (int nt = 0; nt < 2; nt++)
            #pragma unroll
            for (int e = 0; e < 4; e++) d2[nt][e] = 0.f;
        MMA16816(d2[0], hf, &b2f[0][0]);
        MMA16816(d2[1], hf, &b2f[0][2]);
    };
    auto p3f = [&](float (&d2)[2][4], int g) {
        #pragma unroll
        for (int nt = 0; nt < 2; nt++) {
            int col = n0 + 8 * nt + 2 * tig;
            #pragma unroll
            for (int rr = 0; rr < 2; rr++) {
                int row = g * 16 + rr * 8 + gid;
                float v0 = d2[nt][2 * rr]     + b2b[nt].x;
                float v1 = d2[nt][2 * rr + 1] + b2b[nt].y;
                float2 yp = yreg[g][nt][rr];
                float o0, o1;
                if (!is_real) {
                    float e = exp_t(DT * v0);
                    float c = cos_t(DT * v1);
                    float s = sin_t(DT * v1);
                    o0 = e * (c * yp.x - s * yp.y);
                    o1 = e * (s * yp.x + c * yp.y);
                } else {
                    o0 = yp.x * exp_t(DT * v0);
                    o1 = yp.y * exp_t(DT * v1);
                }
                yreg[g][nt][rr] = make_float2(o0, o1);
                *(__half2*)&y_h[row * H_STRIDE + col] = __floats2half2_rn(o0, o1);
                float2 ov = make_float2(o0, o1);
                STCG_F2(outp + (size_t)(g * 16 + rr * 8) * T_TOT * KDIM + nt * 8, ov);
            }
        }
    };

    // ---- pipeline prologue: bring group A to "h ready" state for t=0 ----
    own1f(d1A, 0);
    __syncthreads();             // init y_h visible
    #pragma unroll
    for (int i = 0; i < 11; i++) {
        int kk = i + (i >= wrp);
        uint32_t a[4];
        LDSM4(a, yh_u + kk * 32);
        MMA16816(d1A[0], a, &b1f[i+1][0]);
        MMA16816(d1A[1], a, &b1f[i+1][2]);
    }
    e1f(d1A, hf2A, 0);
    own2f(d2A, hf2A);
    own1f(d1B, 1);

    for (int t = 0; t < T_TOT; t++) {
        __syncthreads();   // BAR1: h_h(A,t) + y_h(B,t) visible

        // ---- SEG1: W2(A) interleaved with W1(B) — two independent chains ----
        if (!is_real) {
            #pragma unroll
            for (int i = 0; i < 11; i++) {
                if (i < 7) {
                    int kk = i + (i >= wrp);
                    uint32_t a[4];
                    LDSM4(a, hh_u + kk * 32);                 // h group A
                    MMA16816(d2A[0], a, &b2f[i+1][0]);
                    MMA16816(d2A[1], a, &b2f[i+1][2]);
                }
                int kk1 = i + (i >= wrp);
                uint32_t b[4];
                LDSM4(b, yh_u + GOFF + kk1 * 32);             // y group B
                MMA16816(d1B[0], b, &b1f[i+1][0]);
                MMA16816(d1B[1], b, &b1f[i+1][2]);
            }
        } else {
            #pragma unroll
            for (int i = 0; i < 11; i++) {
                if (i < 3) {
                    int kk = i + (i >= rw);
                    uint32_t a[4];
                    LDSM4(a, hh_u + 256 + kk * 32);
                    MMA16816(d2A[0], a, &b2f[i+1][0]);
                    MMA16816(d2A[1], a, &b2f[i+1][2]);
                }
                int kk1 = i + (i >= wrp);
                uint32_t b[4];
                LDSM4(b, yh_u + GOFF + kk1 * 32);
                MMA16816(d1B[0], b, &b1f[i+1][0]);
                MMA16816(d1B[1], b, &b1f[i+1][2]);
            }
        }
        p3f(d2A, 0);           // update yreg A, write y_h(A,t+1), store A
        e1f(d1B, hf2B, 1);     // h_h(B,t) + hf2B
        own2f(d2B, hf2B);
        own1f(d1A, 0);         // own chunk for W1(A,t+1) from fresh yreg A

        __syncthreads();   // BAR2: h_h(B,t) + y_h(A,t+1) visible

        // ---- SEG2: W2(B) interleaved with W1(A,t+1) ----
        if (!is_real) {
            #pragma unroll
            for (int i = 0; i < 11; i++) {
                if (i < 7) {
                    int kk = i + (i >= wrp);
                    uint32_t a[4];
                    LDSM4(a, hh_u + GOFF + kk * 32);          // h group B
                    MMA16816(d2B[0], a, &b2f[i+1][0]);
                    MMA16816(d2B[1], a, &b2f[i+1][2]);
                }
                int kk1 = i + (i >= wrp);
                uint32_t b[4];
                LDSM4(b, yh_u + kk1 * 32);                    // y group A (t+1)
                MMA16816(d1A[0], b, &b1f[i+1][0]);
                MMA16816(d1A[1], b, &b1f[i+1][2]);
            }
        } else {
            #pragma unroll
            for (int i = 0; i < 11; i++) {
                if (i < 3) {
                    int kk = i + (i >= rw);
                    uint32_t a[4];
                    LDSM4(a, hh_u + GOFF + 256 + kk * 32);
                    MMA16816(d2B[0], a, &b2f[i+1][0]);
                    MMA16816(d2B[1], a, &b2f[i+1][2]);
                }
                int kk1 = i + (i >= wrp);
                uint32_t b[4];
                LDSM4(b, yh_u + kk1 * 32);
                MMA16816(d1A[0], b, &b1f[i+1][0]);
                MMA16816(d1A[1], b, &b1f[i+1][2]);
            }
        }
        p3f(d2B, 1);           // update yreg B, write y_h(B,t+1), store B
        e1f(d1A, hf2A, 0);     // h_h(A,t+1) + hf2A (harmless extra at t = T-1)
        own2f(d2A, hf2A);
        own1f(d1B, 1);

        outp += KDIM;
    }
}

extern "C" void kernel_launch(void* const* d_in, const int* in_sizes, int n_in,
                              void* d_out, int out_size)
{
    const float* x   = (const float*)d_in[0];
    const float* cW1 = (const float*)d_in[1];
    const float* cb1 = (const float*)d_in[2];
    const float* cW2 = (const float*)d_in[3];
    const float* cb2 = (const float*)d_in[4];
    const float* rW1 = (const float*)d_in[5];
    const float* rb1 = (const float*)d_in[6];
    const float* rW2 = (const float*)d_in[7];
    const float* rb2 = (const float*)d_in[8];
    float* out = (float*)d_out;

    pack_weights<<<(192 * 192 + 255) / 256, 256>>>(cW1, cb1, cW2, cb2, rW1, rb1, rW2, rb2);

    cudaFuncSetAttribute(koopman_mma, cudaFuncAttributeMaxDynamicSharedMemorySize, SMEM_TOTAL);
    koopman_mma<<<NGRID, NTH, SMEM_TOTAL>>>(x, out);
}